// round 5
// baseline (speedup 1.0000x reference)
#include <cuda_runtime.h>
#include <cuda_fp16.h>
#include <cstdint>

#define NV 50000
#define NE 1600000

// ---------------- scratch ----------------
__device__ __align__(16) __half g_Xh[NV * 128];     // x in fp16
__device__ __align__(16) __half g_A[NV * 512];      // [x | sage | gcn | gat] layer1 GEMM input
__device__ __align__(16) __half g_Hh[NV * 128];     // layer1 output (pre-BN), fp16
__device__ __align__(16) __half g_P2h[NV * 160];    // layer2 GEMM output, fp16
__device__ __align__(16) __half g_W1h[128 * 512];   // [n][k]
__device__ __align__(16) __half g_W2h[160 * 128];   // [n][k]
__device__ float g_bias1[128];
__device__ int g_indeg[NV];
__device__ int g_outdeg[NV];
__device__ int g_cursor[NV];
__device__ int g_rowofs[NV + 1];
__device__ int g_srcs[NE];
__device__ float g_ns[NV], g_nd[NV], g_invd[NV];
__device__ float g_el1[NV], g_er1[NV], g_el2[NV], g_er2[NV];
__device__ float g_wl1[128], g_wr1[128];
__device__ float g_bnsum[128], g_bnsq[128], g_bnsc[128], g_bnsh[128];
__device__ float g_w1[3], g_w2[3];

// ---------------- helpers ----------------
__device__ __forceinline__ float lrelu(float x) { return x > 0.f ? x : 0.2f * x; }
__device__ __forceinline__ float warp_max(float v) {
    #pragma unroll
    for (int o = 16; o; o >>= 1) v = fmaxf(v, __shfl_xor_sync(0xffffffffu, v, o));
    return v;
}
__device__ __forceinline__ float warp_sum(float v) {
    #pragma unroll
    for (int o = 16; o; o >>= 1) v += __shfl_xor_sync(0xffffffffu, v, o);
    return v;
}
__device__ __forceinline__ float4 shfl4(float4 v, int src) {
    float4 r;
    r.x = __shfl_sync(0xffffffffu, v.x, src);
    r.y = __shfl_sync(0xffffffffu, v.y, src);
    r.z = __shfl_sync(0xffffffffu, v.z, src);
    r.w = __shfl_sync(0xffffffffu, v.w, src);
    return r;
}
__device__ __forceinline__ uint2 pack4h(float a, float b, float c, float d) {
    __half2 h0 = __floats2half2_rn(a, b), h1 = __floats2half2_rn(c, d);
    uint2 r;
    r.x = *(uint32_t*)&h0;
    r.y = *(uint32_t*)&h1;
    return r;
}
__device__ __forceinline__ void unpack4h(uint2 p, float4& f) {
    float2 a = __half22float2(*(__half2*)&p.x);
    float2 b = __half22float2(*(__half2*)&p.y);
    f.x = a.x; f.y = a.y; f.z = b.x; f.w = b.y;
}
__device__ __forceinline__ void mma_f16(float c[4], const uint32_t a[4], const uint32_t b[2]) {
    asm volatile(
        "mma.sync.aligned.m16n8k16.row.col.f32.f16.f16.f32 "
        "{%0,%1,%2,%3}, {%4,%5,%6,%7}, {%8,%9}, {%0,%1,%2,%3};"
        : "+f"(c[0]), "+f"(c[1]), "+f"(c[2]), "+f"(c[3])
        : "r"(a[0]), "r"(a[1]), "r"(a[2]), "r"(a[3]), "r"(b[0]), "r"(b[1]));
}

// ---------------- setup ----------------
__global__ void k_zero(const float* __restrict__ cw1, const float* __restrict__ cw2) {
    int i = blockIdx.x * blockDim.x + threadIdx.x;
    if (i < NV) { g_indeg[i] = 0; g_outdeg[i] = 0; g_cursor[i] = 0; }
    if (i < 128) { g_bnsum[i] = 0.f; g_bnsq[i] = 0.f; }
    if (i == 0) {
        float s1 = cw1[0] + cw1[1] + cw1[2];
        g_w1[0] = cw1[0] / s1; g_w1[1] = cw1[1] / s1; g_w1[2] = cw1[2] / s1;
        float s2 = cw2[0] + cw2[1] + cw2[2];
        g_w2[0] = cw2[0] / s2; g_w2[1] = cw2[1] / s2; g_w2[2] = cw2[2] / s2;
    }
}

__global__ void k_deg(const int* __restrict__ src, const int* __restrict__ dst) {
    int i = blockIdx.x * blockDim.x + threadIdx.x;
    if (i < NE) {
        atomicAdd(&g_indeg[dst[i]], 1);
        atomicAdd(&g_outdeg[src[i]], 1);
    }
}

// single-pass scan + node factors
__global__ void k_scan() {
    int t = threadIdx.x;
    const int CH = (NV + 1023) / 1024;
    int b0 = t * CH;
    int b1 = min(b0 + CH, NV);
    int sum = 0;
    for (int i = b0; i < b1; i++) sum += g_indeg[i];
    __shared__ int wsum[32];
    int lane = t & 31, wid = t >> 5;
    int v = sum;
    #pragma unroll
    for (int o = 1; o < 32; o <<= 1) {
        int u = __shfl_up_sync(0xffffffffu, v, o);
        if (lane >= o) v += u;
    }
    if (lane == 31) wsum[wid] = v;
    __syncthreads();
    if (wid == 0) {
        int wv = wsum[lane];
        #pragma unroll
        for (int o = 1; o < 32; o <<= 1) {
            int u = __shfl_up_sync(0xffffffffu, wv, o);
            if (lane >= o) wv += u;
        }
        wsum[lane] = wv;
    }
    __syncthreads();
    int excl = v - sum + (wid > 0 ? wsum[wid - 1] : 0);
    int run = excl;
    for (int i = b0; i < b1; i++) { g_rowofs[i] = run; run += g_indeg[i]; }
    if (t == 1023) g_rowofs[NV] = run;
    // node factors
    for (int i = b0; i < b1; i++) {
        float di = fmaxf((float)g_indeg[i], 1.f);
        float doo = fmaxf((float)g_outdeg[i], 1.f);
        g_nd[i] = rsqrtf(di);
        g_ns[i] = rsqrtf(doo);
        g_invd[i] = 1.f / di;
    }
}

__global__ void k_scatter(const int* __restrict__ src, const int* __restrict__ dst) {
    int i = blockIdx.x * blockDim.x + threadIdx.x;
    if (i < NE) {
        int d = dst[i];
        int pos = g_rowofs[d] + atomicAdd(&g_cursor[d], 1);
        g_srcs[pos] = src[i];
    }
}

// W1h[n][k] fp16, scaled combined weights (K=512)
__global__ void k_copyW1(const float* __restrict__ ws, const float* __restrict__ wn,
                         const float* __restrict__ wg, const float* __restrict__ wa,
                         const float* __restrict__ b11, const float* __restrict__ b12,
                         const float* __restrict__ b13) {
    int i = blockIdx.x * blockDim.x + threadIdx.x;
    if (i < 128 * 512) {
        int c = i >> 9, k = i & 511;
        float v;
        if (k < 128)      v = g_w1[0] * ws[k * 128 + c];
        else if (k < 256) v = g_w1[0] * wn[(k - 128) * 128 + c];
        else if (k < 384) v = g_w1[1] * wg[(k - 256) * 128 + c];
        else              v = g_w1[2] * wa[(k - 384) * 128 + c];
        g_W1h[i] = __float2half_rn(v);
    }
    if (i < 128)
        g_bias1[i] = g_w1[0] * b11[i] + g_w1[1] * b12[i] + g_w1[2] * b13[i];
}

// W2h[n][k] fp16
__global__ void k_copyW2(const float* __restrict__ ws, const float* __restrict__ wn,
                         const float* __restrict__ wg, const float* __restrict__ wa) {
    int i = blockIdx.x * blockDim.x + threadIdx.x;
    if (i < 160 * 128) {
        int c = i >> 7, k = i & 127;
        float v;
        if (c < 40)       v = ws[k * 40 + c];
        else if (c < 80)  v = wn[k * 40 + (c - 40)];
        else if (c < 120) v = wg[k * 40 + (c - 80)];
        else              v = wa[k * 40 + (c - 120)];
        g_W2h[i] = __float2half_rn(v);
    }
}

// attention projection vectors
__global__ void k_wvec(const float* __restrict__ w13, const float* __restrict__ al,
                       const float* __restrict__ ar) {
    int k = threadIdx.x;
    float sl = 0.f, sr = 0.f;
    for (int j = 0; j < 128; j++) {
        float w = w13[k * 128 + j];
        sl = fmaf(w, al[j], sl);
        sr = fmaf(w, ar[j], sr);
    }
    g_wl1[k] = sl;
    g_wr1[k] = sr;
}

// attention scalars (fp32 x) + write fp16 copy of x
__global__ void k_eler1(const float* __restrict__ x) {
    int w = (blockIdx.x * blockDim.x + threadIdx.x) >> 5;
    if (w >= NV) return;
    int lane = threadIdx.x & 31;
    float4 u = ((const float4*)(x + (size_t)w * 128))[lane];
    ((uint2*)(g_Xh + (size_t)w * 128))[lane] = pack4h(u.x, u.y, u.z, u.w);
    float4 wl = ((const float4*)g_wl1)[lane];
    float4 wr = ((const float4*)g_wr1)[lane];
    float el = u.x * wl.x + u.y * wl.y + u.z * wl.z + u.w * wl.w;
    float er = u.x * wr.x + u.y * wr.y + u.z * wr.z + u.w * wr.w;
    el = warp_sum(el);
    er = warp_sum(er);
    if (lane == 0) { g_el1[w] = el; g_er1[w] = er; }
}

// layer-1 edge pass: fp16 gather (256B/edge), fp32 accum, fp16 output
__global__ void k_edge1() {
    int w = (blockIdx.x * blockDim.x + threadIdx.x) >> 5;
    if (w >= NV) return;
    int lane = threadIdx.x & 31;
    int s = g_rowofs[w], e = g_rowofs[w + 1];
    float erv = g_er1[w];
    float mx = -1e30f;
    for (int j = s + lane; j < e; j += 32) mx = fmaxf(mx, g_el1[g_srcs[j]]);
    mx = warp_max(mx);
    float me = lrelu(mx + erv);

    float4 fs = make_float4(0, 0, 0, 0), fg = fs, fa = fs;
    float ss = 0.f;
    for (int base = s; base < e; base += 32) {
        int j = base + lane;
        int sj = 0;
        float aw = 0.f, nsv = 0.f;
        if (j < e) {
            sj = g_srcs[j];
            aw = __expf(lrelu(g_el1[sj] + erv) - me);
            nsv = g_ns[sj];
            ss += aw;
        }
        int cnt = min(32, e - base);
        int t = 0;
        for (; t + 4 <= cnt; t += 4) {
            int s0 = __shfl_sync(0xffffffffu, sj, t);
            int s1 = __shfl_sync(0xffffffffu, sj, t + 1);
            int s2 = __shfl_sync(0xffffffffu, sj, t + 2);
            int s3 = __shfl_sync(0xffffffffu, sj, t + 3);
            float A0 = __shfl_sync(0xffffffffu, aw, t);
            float A1 = __shfl_sync(0xffffffffu, aw, t + 1);
            float A2 = __shfl_sync(0xffffffffu, aw, t + 2);
            float A3 = __shfl_sync(0xffffffffu, aw, t + 3);
            float N0 = __shfl_sync(0xffffffffu, nsv, t);
            float N1 = __shfl_sync(0xffffffffu, nsv, t + 1);
            float N2 = __shfl_sync(0xffffffffu, nsv, t + 2);
            float N3 = __shfl_sync(0xffffffffu, nsv, t + 3);
            uint2 p0 = ((const uint2*)(g_Xh + (size_t)s0 * 128))[lane];
            uint2 p1 = ((const uint2*)(g_Xh + (size_t)s1 * 128))[lane];
            uint2 p2 = ((const uint2*)(g_Xh + (size_t)s2 * 128))[lane];
            uint2 p3 = ((const uint2*)(g_Xh + (size_t)s3 * 128))[lane];
            float4 u0, u1, u2, u3;
            unpack4h(p0, u0); unpack4h(p1, u1); unpack4h(p2, u2); unpack4h(p3, u3);
            fs.x += u0.x + u1.x + u2.x + u3.x;
            fs.y += u0.y + u1.y + u2.y + u3.y;
            fs.z += u0.z + u1.z + u2.z + u3.z;
            fs.w += u0.w + u1.w + u2.w + u3.w;
            fg.x = fmaf(N0, u0.x, fmaf(N1, u1.x, fmaf(N2, u2.x, fmaf(N3, u3.x, fg.x))));
            fg.y = fmaf(N0, u0.y, fmaf(N1, u1.y, fmaf(N2, u2.y, fmaf(N3, u3.y, fg.y))));
            fg.z = fmaf(N0, u0.z, fmaf(N1, u1.z, fmaf(N2, u2.z, fmaf(N3, u3.z, fg.z))));
            fg.w = fmaf(N0, u0.w, fmaf(N1, u1.w, fmaf(N2, u2.w, fmaf(N3, u3.w, fg.w))));
            fa.x = fmaf(A0, u0.x, fmaf(A1, u1.x, fmaf(A2, u2.x, fmaf(A3, u3.x, fa.x))));
            fa.y = fmaf(A0, u0.y, fmaf(A1, u1.y, fmaf(A2, u2.y, fmaf(A3, u3.y, fa.y))));
            fa.z = fmaf(A0, u0.z, fmaf(A1, u1.z, fmaf(A2, u2.z, fmaf(A3, u3.z, fa.z))));
            fa.w = fmaf(A0, u0.w, fmaf(A1, u1.w, fmaf(A2, u2.w, fmaf(A3, u3.w, fa.w))));
        }
        for (; t < cnt; t++) {
            int sv = __shfl_sync(0xffffffffu, sj, t);
            float a = __shfl_sync(0xffffffffu, aw, t);
            float nv = __shfl_sync(0xffffffffu, nsv, t);
            uint2 p = ((const uint2*)(g_Xh + (size_t)sv * 128))[lane];
            float4 u;
            unpack4h(p, u);
            fs.x += u.x; fs.y += u.y; fs.z += u.z; fs.w += u.w;
            fg.x = fmaf(nv, u.x, fg.x); fg.y = fmaf(nv, u.y, fg.y);
            fg.z = fmaf(nv, u.z, fg.z); fg.w = fmaf(nv, u.w, fg.w);
            fa.x = fmaf(a, u.x, fa.x); fa.y = fmaf(a, u.y, fa.y);
            fa.z = fmaf(a, u.z, fa.z); fa.w = fmaf(a, u.w, fa.w);
        }
    }
    ss = warp_sum(ss);
    float invd = g_invd[w], ndv = g_nd[w];
    float invs = 1.f / fmaxf(ss, 1e-9f);
    uint2* row = (uint2*)(g_A + (size_t)w * 512);
    row[lane] = ((const uint2*)(g_Xh + (size_t)w * 128))[lane];  // self: direct copy
    row[32 + lane] = pack4h(fs.x * invd, fs.y * invd, fs.z * invd, fs.w * invd);
    row[64 + lane] = pack4h(fg.x * ndv, fg.y * ndv, fg.z * ndv, fg.w * ndv);
    row[96 + lane] = pack4h(fa.x * invs, fa.y * invs, fa.z * invs, fa.w * invs);
}

// ---------------- fp16 tensor-core GEMM (m16n8k16) ----------------
// C[M][Ncols](half) = A[M][KDIM](half) @ Bt[Ncols][KDIM](half)^T
// TRANS: BN+ReLU applied to A on load. STATS: fused bias + BN statistics (layer1).
template <int KDIM, bool TRANS, bool STATS>
__global__ __launch_bounds__(256) void gemm_hf(
    const __half* __restrict__ A, const __half* __restrict__ Bt,
    __half* __restrict__ C, int M, int Ncols) {
    __shared__ uint32_t As2[128][12];  // 8 half2 data + 4 pad
    __shared__ uint32_t Bs2[128][12];
    __shared__ float s_sc[128], s_sh[128], s_b[128];
    int tid = threadIdx.x;
    if (TRANS && tid < 128) { s_sc[tid] = g_bnsc[tid]; s_sh[tid] = g_bnsh[tid]; }
    if (STATS && tid < 128) s_b[tid] = g_bias1[tid];
    if (TRANS || STATS) __syncthreads();

    int m0 = blockIdx.x * 128, n0 = blockIdx.y * 128;
    int wid = tid >> 5, lane = tid & 31;
    int mw = (wid & 3) * 32, nw = (wid >> 2) * 64;
    int qr = lane >> 2, qc = lane & 3;
    float acc[2][8][4];
    #pragma unroll
    for (int mi = 0; mi < 2; mi++)
        #pragma unroll
        for (int nj = 0; nj < 8; nj++)
            #pragma unroll
            for (int q = 0; q < 4; q++) acc[mi][nj][q] = 0.f;

    int lr = tid >> 1;         // 0..127
    int lk = (tid & 1) * 8;    // half offset 0 or 8

    for (int kk = 0; kk < KDIM; kk += 16) {
        {
            int grow = m0 + lr;
            uint4 va = make_uint4(0, 0, 0, 0);
            if (grow < M) va = *(const uint4*)(A + (size_t)grow * KDIM + kk + lk);
            if (TRANS) {
                __half2* hp = (__half2*)&va;
                #pragma unroll
                for (int q = 0; q < 4; q++) {
                    float2 f = __half22float2(hp[q]);
                    int kb = kk + lk + q * 2;
                    f.x = fmaxf(fmaf(f.x, s_sc[kb], s_sh[kb]), 0.f);
                    f.y = fmaxf(fmaf(f.y, s_sc[kb + 1], s_sh[kb + 1]), 0.f);
                    hp[q] = __floats2half2_rn(f.x, f.y);
                }
            }
            *(uint4*)&As2[lr][lk >> 1] = va;
        }
        {
            int gn = n0 + lr;
            uint4 vb = make_uint4(0, 0, 0, 0);
            if (gn < Ncols) vb = *(const uint4*)(Bt + (size_t)gn * KDIM + kk + lk);
            *(uint4*)&Bs2[lr][lk >> 1] = vb;
        }
        __syncthreads();
        uint32_t af[2][4];
        #pragma unroll
        for (int mi = 0; mi < 2; mi++) {
            int rb = mw + mi * 16;
            af[mi][0] = As2[rb + qr][qc];
            af[mi][1] = As2[rb + 8 + qr][qc];
            af[mi][2] = As2[rb + qr][4 + qc];
            af[mi][3] = As2[rb + 8 + qr][4 + qc];
        }
        uint32_t bf[8][2];
        #pragma unroll
        for (int nj = 0; nj < 8; nj++) {
            int nb = nw + nj * 8;
            bf[nj][0] = Bs2[nb + qr][qc];
            bf[nj][1] = Bs2[nb + qr][4 + qc];
        }
        #pragma unroll
        for (int mi = 0; mi < 2; mi++)
            #pragma unroll
            for (int nj = 0; nj < 8; nj++)
                mma_f16(acc[mi][nj], af[mi], bf[nj]);
        __syncthreads();
    }
    // epilogue: store + (optional) fused BN stats
    float st[8][4];
    if (STATS) {
        #pragma unroll
        for (int nj = 0; nj < 8; nj++)
            #pragma unroll
            for (int q = 0; q < 4; q++) st[nj][q] = 0.f;
    }
    #pragma unroll
    for (int mi = 0; mi < 2; mi++) {
        #pragma unroll
        for (int nj = 0; nj < 8; nj++) {
            int colL = nw + nj * 8 + qc * 2;
            int col = n0 + colL;
            int r0 = m0 + mw + mi * 16 + qr;
            int r1 = r0 + 8;
            float v00 = acc[mi][nj][0], v01 = acc[mi][nj][1];
            float v10 = acc[mi][nj][2], v11 = acc[mi][nj][3];
            if (STATS) {
                float b0 = s_b[colL], b1 = s_b[colL + 1];
                v00 += b0; v01 += b1; v10 += b0; v11 += b1;
            }
            if (col < Ncols) {
                if (r0 < M) *(__half2*)(C + (size_t)r0 * Ncols + col) = __floats2half2_rn(v00, v01);
                if (r1 < M) *(__half2*)(C + (size_t)r1 * Ncols + col) = __floats2half2_rn(v10, v11);
            }
            if (STATS) {
                if (r0 >= M) { v00 = 0.f; v01 = 0.f; }
                if (r1 >= M) { v10 = 0.f; v11 = 0.f; }
                st[nj][0] += v00 + v10;
                st[nj][1] += v01 + v11;
                st[nj][2] += v00 * v00 + v10 * v10;
                st[nj][3] += v01 * v01 + v11 * v11;
            }
        }
    }
    if (STATS) {
        #pragma unroll
        for (int nj = 0; nj < 8; nj++) {
            float s0 = st[nj][0], s1 = st[nj][1], q0 = st[nj][2], q1 = st[nj][3];
            #pragma unroll
            for (int o = 4; o < 32; o <<= 1) {
                s0 += __shfl_xor_sync(0xffffffffu, s0, o);
                s1 += __shfl_xor_sync(0xffffffffu, s1, o);
                q0 += __shfl_xor_sync(0xffffffffu, q0, o);
                q1 += __shfl_xor_sync(0xffffffffu, q1, o);
            }
            if (lane < 4) {
                int col = nw + nj * 8 + lane * 2;
                atomicAdd(&g_bnsum[col], s0);
                atomicAdd(&g_bnsum[col + 1], s1);
                atomicAdd(&g_bnsq[col], q0);
                atomicAdd(&g_bnsq[col + 1], q1);
            }
        }
    }
}

// ---------------- BN finalize ----------------
__global__ void k_bnfin(const float* __restrict__ g, const float* __restrict__ be) {
    int t = threadIdx.x;
    if (t < 128) {
        float mean = g_bnsum[t] * (1.f / NV);
        float var = g_bnsq[t] * (1.f / NV) - mean * mean;
        float sc = g[t] * rsqrtf(var + 1e-5f);
        g_bnsc[t] = sc;
        g_bnsh[t] = be[t] - mean * sc;
    }
}

// ---------------- layer-2 epilogue: GAT dots + GCN prescale ----------------
__global__ void k_post2(const float* __restrict__ al, const float* __restrict__ ar) {
    int w = (blockIdx.x * blockDim.x + threadIdx.x) >> 5;
    if (w >= NV) return;
    int lane = threadIdx.x & 31;
    __half* row = g_P2h + (size_t)w * 160;
    float el = 0.f, er = 0.f;
    for (int c = lane; c < 40; c += 32) {
        float f = __half2float(row[120 + c]);
        el = fmaf(f, al[c], el);
        er = fmaf(f, ar[c], er);
    }
    el = warp_sum(el);
    er = warp_sum(er);
    if (lane == 0) { g_el2[w] = el; g_er2[w] = er; }
    float nsv = g_ns[w];
    for (int c = lane; c < 40; c += 32)
        row[80 + c] = __float2half_rn(__half2float(row[80 + c]) * nsv);
}

// ---------------- layer-2 edge aggregation + combine + log_softmax ----------------
__global__ void k_agg2(const float* __restrict__ b21, const float* __restrict__ b22,
                       const float* __restrict__ b23, float* __restrict__ out) {
    int w = (blockIdx.x * blockDim.x + threadIdx.x) >> 5;
    if (w >= NV) return;
    int lane = threadIdx.x & 31;
    int s = g_rowofs[w], e = g_rowofs[w + 1];
    float erv = g_er2[w];
    float mx = -1e30f;
    for (int j = s + lane; j < e; j += 32) mx = fmaxf(mx, g_el2[g_srcs[j]]);
    mx = warp_max(mx);
    float me = lrelu(mx + erv);

    float4 acc = make_float4(0, 0, 0, 0);
    float ss = 0.f;
    bool vec = (lane < 30);
    float gatsel = (lane >= 20 && lane < 30) ? 1.f : 0.f;
    for (int base = s; base < e; base += 32) {
        int j = base + lane;
        int sj = 0;
        float aw = 0.f;
        if (j < e) {
            sj = g_srcs[j];
            aw = __expf(lrelu(g_el2[sj] + erv) - me);
            ss += aw;
        }
        int cnt = min(32, e - base);
        int t = 0;
        for (; t + 4 <= cnt; t += 4) {
            int s0 = __shfl_sync(0xffffffffu, sj, t);
            int s1 = __shfl_sync(0xffffffffu, sj, t + 1);
            int s2 = __shfl_sync(0xffffffffu, sj, t + 2);
            int s3 = __shfl_sync(0xffffffffu, sj, t + 3);
            float A0 = __shfl_sync(0xffffffffu, aw, t);
            float A1 = __shfl_sync(0xffffffffu, aw, t + 1);
            float A2 = __shfl_sync(0xffffffffu, aw, t + 2);
            float A3 = __shfl_sync(0xffffffffu, aw, t + 3);
            if (vec) {
                float m0 = gatsel ? A0 : 1.f;
                float m1 = gatsel ? A1 : 1.f;
                float m2 = gatsel ? A2 : 1.f;
                float m3 = gatsel ? A3 : 1.f;
                uint2 p0 = ((const uint2*)(g_P2h + (size_t)s0 * 160 + 40))[lane];
                uint2 p1 = ((const uint2*)(g_P2h + (size_t)s1 * 160 + 40))[lane];
                uint2 p2 = ((const uint2*)(g_P2h + (size_t)s2 * 160 + 40))[lane];
                uint2 p3 = ((const uint2*)(g_P2h + (size_t)s3 * 160 + 40))[lane];
                float4 u0, u1, u2, u3;
                unpack4h(p0, u0); unpack4h(p1, u1); unpack4h(p2, u2); unpack4h(p3, u3);
                acc.x = fmaf(m0, u0.x, fmaf(m1, u1.x, fmaf(m2, u2.x, fmaf(m3, u3.x, acc.x))));
                acc.y = fmaf(m0, u0.y, fmaf(m1, u1.y, fmaf(m2, u2.y, fmaf(m3, u3.y, acc.y))));
                acc.z = fmaf(m0, u0.z, fmaf(m1, u1.z, fmaf(m2, u2.z, fmaf(m3, u3.z, acc.z))));
                acc.w = fmaf(m0, u0.w, fmaf(m1, u1.w, fmaf(m2, u2.w, fmaf(m3, u3.w, acc.w))));
            }
        }
        for (; t < cnt; t++) {
            int sv = __shfl_sync(0xffffffffu, sj, t);
            float a = __shfl_sync(0xffffffffu, aw, t);
            if (vec) {
                float m = gatsel ? a : 1.f;
                uint2 p = ((const uint2*)(g_P2h + (size_t)sv * 160 + 40))[lane];
                float4 u;
                unpack4h(p, u);
                acc.x = fmaf(m, u.x, acc.x);
                acc.y = fmaf(m, u.y, acc.y);
                acc.z = fmaf(m, u.z, acc.z);
                acc.w = fmaf(m, u.w, acc.w);
            }
        }
    }
    ss = warp_sum(ss);
    float invd = g_invd[w], ndv = g_nd[w];
    float invs = 1.f / fmaxf(ss, 1e-9f);
    int cs = (lane < 10) ? lane : 0;
    float4 sg = shfl4(acc, cs);
    float4 gc = shfl4(acc, cs + 10);
    float4 ga = shfl4(acc, cs + 20);
    float w0 = g_w2[0], w1 = g_w2[1], w2 = g_w2[2];
    float4 val = make_float4(0, 0, 0, 0);
    float lm = -1e30f;
    if (lane < 10) {
        uint2 ps = ((const uint2*)(g_P2h + (size_t)w * 160))[lane];
        float4 self;
        unpack4h(ps, self);
        float4 bs = ((const float4*)b21)[lane];
        float4 bg = ((const float4*)b22)[lane];
        float4 ba = ((const float4*)b23)[lane];
        val.x = w0 * (self.x + sg.x * invd + bs.x) + w1 * (gc.x * ndv + bg.x) + w2 * (ga.x * invs + ba.x);
        val.y = w0 * (self.y + sg.y * invd + bs.y) + w1 * (gc.y * ndv + bg.y) + w2 * (ga.y * invs + ba.y);
        val.z = w0 * (self.z + sg.z * invd + bs.z) + w1 * (gc.z * ndv + bg.z) + w2 * (ga.z * invs + ba.z);
        val.w = w0 * (self.w + sg.w * invd + bs.w) + w1 * (gc.w * ndv + bg.w) + w2 * (ga.w * invs + ba.w);
        lm = fmaxf(fmaxf(val.x, val.y), fmaxf(val.z, val.w));
    }
    #pragma unroll
    for (int o = 8; o; o >>= 1) lm = fmaxf(lm, __shfl_xor_sync(0xffffffffu, lm, o));
    float se = 0.f;
    if (lane < 10)
        se = __expf(val.x - lm) + __expf(val.y - lm) + __expf(val.z - lm) + __expf(val.w - lm);
    #pragma unroll
    for (int o = 8; o; o >>= 1) se += __shfl_xor_sync(0xffffffffu, se, o);
    float lse = lm + logf(se);
    if (lane < 10) {
        float4 r = make_float4(val.x - lse, val.y - lse, val.z - lse, val.w - lse);
        ((float4*)(out + (size_t)w * 40))[lane] = r;
    }
}

// ---------------- launch ----------------
extern "C" void kernel_launch(void* const* d_in, const int* in_sizes, int n_in,
                              void* d_out, int out_size) {
    const float* x    = (const float*)d_in[0];
    const int*   src  = (const int*)d_in[1];
    const int*   dst  = (const int*)d_in[2];
    const float* w11s = (const float*)d_in[3];
    const float* w11n = (const float*)d_in[4];
    const float* b11  = (const float*)d_in[5];
    const float* w12  = (const float*)d_in[6];
    const float* b12  = (const float*)d_in[7];
    const float* w13  = (const float*)d_in[8];
    const float* a13l = (const float*)d_in[9];
    const float* a13r = (const float*)d_in[10];
    const float* b13  = (const float*)d_in[11];
    const float* cw1  = (const float*)d_in[12];
    const float* g    = (const float*)d_in[13];
    const float* be   = (const float*)d_in[14];
    const float* w21s = (const float*)d_in[15];
    const float* w21n = (const float*)d_in[16];
    const float* b21  = (const float*)d_in[17];
    const float* w22  = (const float*)d_in[18];
    const float* b22  = (const float*)d_in[19];
    const float* w23  = (const float*)d_in[20];
    const float* a23l = (const float*)d_in[21];
    const float* a23r = (const float*)d_in[22];
    const float* b23  = (const float*)d_in[23];
    const float* cw2  = (const float*)d_in[24];
    float* out = (float*)d_out;

    __half* dA;  cudaGetSymbolAddress((void**)&dA,  g_A);
    __half* dH;  cudaGetSymbolAddress((void**)&dH,  g_Hh);
    __half* dP2; cudaGetSymbolAddress((void**)&dP2, g_P2h);
    __half* dW1; cudaGetSymbolAddress((void**)&dW1, g_W1h);
    __half* dW2; cudaGetSymbolAddress((void**)&dW2, g_W2h);

    const int TPB = 256;
    int nblkV = (NV + TPB - 1) / TPB;
    int nblkE = (NE + TPB - 1) / TPB;
    int nblkW = (NV + 7) / 8;  // one warp per node

    k_zero<<<nblkV, TPB>>>(cw1, cw2);
    k_deg<<<nblkE, TPB>>>(src, dst);
    k_scan<<<1, 1024>>>();
    k_scatter<<<nblkE, TPB>>>(src, dst);
    k_copyW1<<<(128 * 512) / TPB, TPB>>>(w11s, w11n, w12, w13, b11, b12, b13);
    k_copyW2<<<(160 * 128 + TPB - 1) / TPB, TPB>>>(w21s, w21n, w22, w23);
    k_wvec<<<1, 128>>>(w13, a13l, a13r);

    k_eler1<<<nblkW, TPB>>>(x);
    k_edge1<<<nblkW, TPB>>>();
    gemm_hf<512, false, true><<<dim3((NV + 127) / 128, 1), 256>>>(dA, dW1, dH, NV, 128);

    k_bnfin<<<1, 128>>>(g, be);

    gemm_hf<128, true, false><<<dim3((NV + 127) / 128, 2), 256>>>(dH, dW2, dP2, NV, 160);
    k_post2<<<nblkW, TPB>>>(a23l, a23r);
    k_agg2<<<nblkW, TPB>>>(b21, b22, b23, out);
}

// round 6
// speedup vs baseline: 1.0035x; 1.0035x over previous
#include <cuda_runtime.h>
#include <cuda_fp16.h>
#include <cstdint>

#define NV 50000
#define NE 1600000

// ---------------- scratch ----------------
__device__ __align__(16) __half g_Xh[NV * 128];     // x in fp16
__device__ __align__(16) __half g_A[NV * 512];      // [x | sage | gcn | gat] layer1 GEMM input
__device__ __align__(16) __half g_Hh[NV * 128];     // layer1 output (pre-BN), fp16
__device__ __align__(16) __half g_P2h[NV * 160];    // layer2 GEMM output, fp16
__device__ __align__(16) __half g_W1h[128 * 512];   // [n][k]
__device__ __align__(16) __half g_W2h[160 * 128];   // [n][k]
__device__ float g_bias1[128];
__device__ int g_indeg[NV];
__device__ int g_outdeg[NV];
__device__ int g_cursor[NV];
__device__ int g_rowofs[NV + 1];
__device__ int g_srcs[NE];
__device__ float g_ns[NV], g_nd[NV], g_invd[NV];
__device__ float g_el1[NV], g_er1[NV], g_el2[NV], g_er2[NV];
__device__ float g_wl1[128], g_wr1[128];
__device__ float g_bnsum[128], g_bnsq[128], g_bnsc[128], g_bnsh[128];
__device__ float g_w1[3], g_w2[3];

// ---------------- helpers ----------------
__device__ __forceinline__ float lrelu(float x) { return x > 0.f ? x : 0.2f * x; }
__device__ __forceinline__ float warp_max(float v) {
    #pragma unroll
    for (int o = 16; o; o >>= 1) v = fmaxf(v, __shfl_xor_sync(0xffffffffu, v, o));
    return v;
}
__device__ __forceinline__ float warp_sum(float v) {
    #pragma unroll
    for (int o = 16; o; o >>= 1) v += __shfl_xor_sync(0xffffffffu, v, o);
    return v;
}
__device__ __forceinline__ float4 shfl4(float4 v, int src) {
    float4 r;
    r.x = __shfl_sync(0xffffffffu, v.x, src);
    r.y = __shfl_sync(0xffffffffu, v.y, src);
    r.z = __shfl_sync(0xffffffffu, v.z, src);
    r.w = __shfl_sync(0xffffffffu, v.w, src);
    return r;
}
__device__ __forceinline__ uint2 pack4h(float a, float b, float c, float d) {
    __half2 h0 = __floats2half2_rn(a, b), h1 = __floats2half2_rn(c, d);
    uint2 r;
    r.x = *(uint32_t*)&h0;
    r.y = *(uint32_t*)&h1;
    return r;
}
__device__ __forceinline__ void unpack4h(uint2 p, float4& f) {
    float2 a = __half22float2(*(__half2*)&p.x);
    float2 b = __half22float2(*(__half2*)&p.y);
    f.x = a.x; f.y = a.y; f.z = b.x; f.w = b.y;
}
__device__ __forceinline__ void mma_f16(float c[4], const uint32_t a[4], const uint32_t b[2]) {
    asm volatile(
        "mma.sync.aligned.m16n8k16.row.col.f32.f16.f16.f32 "
        "{%0,%1,%2,%3}, {%4,%5,%6,%7}, {%8,%9}, {%0,%1,%2,%3};"
        : "+f"(c[0]), "+f"(c[1]), "+f"(c[2]), "+f"(c[3])
        : "r"(a[0]), "r"(a[1]), "r"(a[2]), "r"(a[3]), "r"(b[0]), "r"(b[1]));
}

// ---------------- setup ----------------
__global__ void k_zero(const float* __restrict__ cw1, const float* __restrict__ cw2) {
    int i = blockIdx.x * blockDim.x + threadIdx.x;
    if (i < NV) { g_indeg[i] = 0; g_outdeg[i] = 0; g_cursor[i] = 0; }
    if (i < 128) { g_bnsum[i] = 0.f; g_bnsq[i] = 0.f; }
    if (i == 0) {
        float s1 = cw1[0] + cw1[1] + cw1[2];
        g_w1[0] = cw1[0] / s1; g_w1[1] = cw1[1] / s1; g_w1[2] = cw1[2] / s1;
        float s2 = cw2[0] + cw2[1] + cw2[2];
        g_w2[0] = cw2[0] / s2; g_w2[1] = cw2[1] / s2; g_w2[2] = cw2[2] / s2;
    }
}

__global__ void k_deg(const int* __restrict__ src, const int* __restrict__ dst) {
    int i = blockIdx.x * blockDim.x + threadIdx.x;
    if (i < NE) {
        atomicAdd(&g_indeg[dst[i]], 1);
        atomicAdd(&g_outdeg[src[i]], 1);
    }
}

// single-pass scan + node factors
__global__ void k_scan() {
    int t = threadIdx.x;
    const int CH = (NV + 1023) / 1024;
    int b0 = t * CH;
    int b1 = min(b0 + CH, NV);
    int sum = 0;
    for (int i = b0; i < b1; i++) sum += g_indeg[i];
    __shared__ int wsum[32];
    int lane = t & 31, wid = t >> 5;
    int v = sum;
    #pragma unroll
    for (int o = 1; o < 32; o <<= 1) {
        int u = __shfl_up_sync(0xffffffffu, v, o);
        if (lane >= o) v += u;
    }
    if (lane == 31) wsum[wid] = v;
    __syncthreads();
    if (wid == 0) {
        int wv = wsum[lane];
        #pragma unroll
        for (int o = 1; o < 32; o <<= 1) {
            int u = __shfl_up_sync(0xffffffffu, wv, o);
            if (lane >= o) wv += u;
        }
        wsum[lane] = wv;
    }
    __syncthreads();
    int excl = v - sum + (wid > 0 ? wsum[wid - 1] : 0);
    int run = excl;
    for (int i = b0; i < b1; i++) { g_rowofs[i] = run; run += g_indeg[i]; }
    if (t == 1023) g_rowofs[NV] = run;
    // node factors
    for (int i = b0; i < b1; i++) {
        float di = fmaxf((float)g_indeg[i], 1.f);
        float doo = fmaxf((float)g_outdeg[i], 1.f);
        g_nd[i] = rsqrtf(di);
        g_ns[i] = rsqrtf(doo);
        g_invd[i] = 1.f / di;
    }
}

__global__ void k_scatter(const int* __restrict__ src, const int* __restrict__ dst) {
    int i = blockIdx.x * blockDim.x + threadIdx.x;
    if (i < NE) {
        int d = dst[i];
        int pos = g_rowofs[d] + atomicAdd(&g_cursor[d], 1);
        g_srcs[pos] = src[i];
    }
}

// W1h[n][k] fp16, scaled combined weights (K=512)
__global__ void k_copyW1(const float* __restrict__ ws, const float* __restrict__ wn,
                         const float* __restrict__ wg, const float* __restrict__ wa,
                         const float* __restrict__ b11, const float* __restrict__ b12,
                         const float* __restrict__ b13) {
    int i = blockIdx.x * blockDim.x + threadIdx.x;
    if (i < 128 * 512) {
        int c = i >> 9, k = i & 511;
        float v;
        if (k < 128)      v = g_w1[0] * ws[k * 128 + c];
        else if (k < 256) v = g_w1[0] * wn[(k - 128) * 128 + c];
        else if (k < 384) v = g_w1[1] * wg[(k - 256) * 128 + c];
        else              v = g_w1[2] * wa[(k - 384) * 128 + c];
        g_W1h[i] = __float2half_rn(v);
    }
    if (i < 128)
        g_bias1[i] = g_w1[0] * b11[i] + g_w1[1] * b12[i] + g_w1[2] * b13[i];
}

// W2h[n][k] fp16
__global__ void k_copyW2(const float* __restrict__ ws, const float* __restrict__ wn,
                         const float* __restrict__ wg, const float* __restrict__ wa) {
    int i = blockIdx.x * blockDim.x + threadIdx.x;
    if (i < 160 * 128) {
        int c = i >> 7, k = i & 127;
        float v;
        if (c < 40)       v = ws[k * 40 + c];
        else if (c < 80)  v = wn[k * 40 + (c - 40)];
        else if (c < 120) v = wg[k * 40 + (c - 80)];
        else              v = wa[k * 40 + (c - 120)];
        g_W2h[i] = __float2half_rn(v);
    }
}

// attention projection vectors
__global__ void k_wvec(const float* __restrict__ w13, const float* __restrict__ al,
                       const float* __restrict__ ar) {
    int k = threadIdx.x;
    float sl = 0.f, sr = 0.f;
    for (int j = 0; j < 128; j++) {
        float w = w13[k * 128 + j];
        sl = fmaf(w, al[j], sl);
        sr = fmaf(w, ar[j], sr);
    }
    g_wl1[k] = sl;
    g_wr1[k] = sr;
}

// attention scalars (fp32 x) + write fp16 copy of x
__global__ void k_eler1(const float* __restrict__ x) {
    int w = (blockIdx.x * blockDim.x + threadIdx.x) >> 5;
    if (w >= NV) return;
    int lane = threadIdx.x & 31;
    float4 u = ((const float4*)(x + (size_t)w * 128))[lane];
    ((uint2*)(g_Xh + (size_t)w * 128))[lane] = pack4h(u.x, u.y, u.z, u.w);
    float4 wl = ((const float4*)g_wl1)[lane];
    float4 wr = ((const float4*)g_wr1)[lane];
    float el = u.x * wl.x + u.y * wl.y + u.z * wl.z + u.w * wl.w;
    float er = u.x * wr.x + u.y * wr.y + u.z * wr.z + u.w * wr.w;
    el = warp_sum(el);
    er = warp_sum(er);
    if (lane == 0) { g_el1[w] = el; g_er1[w] = er; }
}

// layer-1 edge pass: fp16 gather (256B/edge), fp32 accum, fp16 output
__global__ void k_edge1() {
    int w = (blockIdx.x * blockDim.x + threadIdx.x) >> 5;
    if (w >= NV) return;
    int lane = threadIdx.x & 31;
    int s = g_rowofs[w], e = g_rowofs[w + 1];
    float erv = g_er1[w];
    float mx = -1e30f;
    for (int j = s + lane; j < e; j += 32) mx = fmaxf(mx, g_el1[g_srcs[j]]);
    mx = warp_max(mx);
    float me = lrelu(mx + erv);

    float4 fs = make_float4(0, 0, 0, 0), fg = fs, fa = fs;
    float ss = 0.f;
    for (int base = s; base < e; base += 32) {
        int j = base + lane;
        int sj = 0;
        float aw = 0.f, nsv = 0.f;
        if (j < e) {
            sj = g_srcs[j];
            aw = __expf(lrelu(g_el1[sj] + erv) - me);
            nsv = g_ns[sj];
            ss += aw;
        }
        int cnt = min(32, e - base);
        int t = 0;
        for (; t + 4 <= cnt; t += 4) {
            int s0 = __shfl_sync(0xffffffffu, sj, t);
            int s1 = __shfl_sync(0xffffffffu, sj, t + 1);
            int s2 = __shfl_sync(0xffffffffu, sj, t + 2);
            int s3 = __shfl_sync(0xffffffffu, sj, t + 3);
            float A0 = __shfl_sync(0xffffffffu, aw, t);
            float A1 = __shfl_sync(0xffffffffu, aw, t + 1);
            float A2 = __shfl_sync(0xffffffffu, aw, t + 2);
            float A3 = __shfl_sync(0xffffffffu, aw, t + 3);
            float N0 = __shfl_sync(0xffffffffu, nsv, t);
            float N1 = __shfl_sync(0xffffffffu, nsv, t + 1);
            float N2 = __shfl_sync(0xffffffffu, nsv, t + 2);
            float N3 = __shfl_sync(0xffffffffu, nsv, t + 3);
            uint2 p0 = ((const uint2*)(g_Xh + (size_t)s0 * 128))[lane];
            uint2 p1 = ((const uint2*)(g_Xh + (size_t)s1 * 128))[lane];
            uint2 p2 = ((const uint2*)(g_Xh + (size_t)s2 * 128))[lane];
            uint2 p3 = ((const uint2*)(g_Xh + (size_t)s3 * 128))[lane];
            float4 u0, u1, u2, u3;
            unpack4h(p0, u0); unpack4h(p1, u1); unpack4h(p2, u2); unpack4h(p3, u3);
            fs.x += u0.x + u1.x + u2.x + u3.x;
            fs.y += u0.y + u1.y + u2.y + u3.y;
            fs.z += u0.z + u1.z + u2.z + u3.z;
            fs.w += u0.w + u1.w + u2.w + u3.w;
            fg.x = fmaf(N0, u0.x, fmaf(N1, u1.x, fmaf(N2, u2.x, fmaf(N3, u3.x, fg.x))));
            fg.y = fmaf(N0, u0.y, fmaf(N1, u1.y, fmaf(N2, u2.y, fmaf(N3, u3.y, fg.y))));
            fg.z = fmaf(N0, u0.z, fmaf(N1, u1.z, fmaf(N2, u2.z, fmaf(N3, u3.z, fg.z))));
            fg.w = fmaf(N0, u0.w, fmaf(N1, u1.w, fmaf(N2, u2.w, fmaf(N3, u3.w, fg.w))));
            fa.x = fmaf(A0, u0.x, fmaf(A1, u1.x, fmaf(A2, u2.x, fmaf(A3, u3.x, fa.x))));
            fa.y = fmaf(A0, u0.y, fmaf(A1, u1.y, fmaf(A2, u2.y, fmaf(A3, u3.y, fa.y))));
            fa.z = fmaf(A0, u0.z, fmaf(A1, u1.z, fmaf(A2, u2.z, fmaf(A3, u3.z, fa.z))));
            fa.w = fmaf(A0, u0.w, fmaf(A1, u1.w, fmaf(A2, u2.w, fmaf(A3, u3.w, fa.w))));
        }
        for (; t < cnt; t++) {
            int sv = __shfl_sync(0xffffffffu, sj, t);
            float a = __shfl_sync(0xffffffffu, aw, t);
            float nv = __shfl_sync(0xffffffffu, nsv, t);
            uint2 p = ((const uint2*)(g_Xh + (size_t)sv * 128))[lane];
            float4 u;
            unpack4h(p, u);
            fs.x += u.x; fs.y += u.y; fs.z += u.z; fs.w += u.w;
            fg.x = fmaf(nv, u.x, fg.x); fg.y = fmaf(nv, u.y, fg.y);
            fg.z = fmaf(nv, u.z, fg.z); fg.w = fmaf(nv, u.w, fg.w);
            fa.x = fmaf(a, u.x, fa.x); fa.y = fmaf(a, u.y, fa.y);
            fa.z = fmaf(a, u.z, fa.z); fa.w = fmaf(a, u.w, fa.w);
        }
    }
    ss = warp_sum(ss);
    float invd = g_invd[w], ndv = g_nd[w];
    float invs = 1.f / fmaxf(ss, 1e-9f);
    uint2* row = (uint2*)(g_A + (size_t)w * 512);
    row[lane] = ((const uint2*)(g_Xh + (size_t)w * 128))[lane];  // self: direct copy
    row[32 + lane] = pack4h(fs.x * invd, fs.y * invd, fs.z * invd, fs.w * invd);
    row[64 + lane] = pack4h(fg.x * ndv, fg.y * ndv, fg.z * ndv, fg.w * ndv);
    row[96 + lane] = pack4h(fa.x * invs, fa.y * invs, fa.z * invs, fa.w * invs);
}

// ---------------- fp16 tensor-core GEMM (m16n8k16) ----------------
// C[M][Ncols](half) = A[M][KDIM](half) @ Bt[Ncols][KDIM](half)^T
// TRANS: BN+ReLU applied to A on load. STATS: fused bias + BN statistics (layer1).
template <int KDIM, bool TRANS, bool STATS>
__global__ __launch_bounds__(256) void gemm_hf(
    const __half* __restrict__ A, const __half* __restrict__ Bt,
    __half* __restrict__ C, int M, int Ncols) {
    __shared__ uint32_t As2[128][12];  // 8 half2 data + 4 pad
    __shared__ uint32_t Bs2[128][12];
    __shared__ float s_sc[128], s_sh[128], s_b[128];
    int tid = threadIdx.x;
    if (TRANS && tid < 128) { s_sc[tid] = g_bnsc[tid]; s_sh[tid] = g_bnsh[tid]; }
    if (STATS && tid < 128) s_b[tid] = g_bias1[tid];
    if (TRANS || STATS) __syncthreads();

    int m0 = blockIdx.x * 128, n0 = blockIdx.y * 128;
    int wid = tid >> 5, lane = tid & 31;
    int mw = (wid & 3) * 32, nw = (wid >> 2) * 64;
    int qr = lane >> 2, qc = lane & 3;
    float acc[2][8][4];
    #pragma unroll
    for (int mi = 0; mi < 2; mi++)
        #pragma unroll
        for (int nj = 0; nj < 8; nj++)
            #pragma unroll
            for (int q = 0; q < 4; q++) acc[mi][nj][q] = 0.f;

    int lr = tid >> 1;         // 0..127
    int lk = (tid & 1) * 8;    // half offset 0 or 8

    for (int kk = 0; kk < KDIM; kk += 16) {
        {
            int grow = m0 + lr;
            uint4 va = make_uint4(0, 0, 0, 0);
            if (grow < M) va = *(const uint4*)(A + (size_t)grow * KDIM + kk + lk);
            if (TRANS) {
                __half2* hp = (__half2*)&va;
                #pragma unroll
                for (int q = 0; q < 4; q++) {
                    float2 f = __half22float2(hp[q]);
                    int kb = kk + lk + q * 2;
                    f.x = fmaxf(fmaf(f.x, s_sc[kb], s_sh[kb]), 0.f);
                    f.y = fmaxf(fmaf(f.y, s_sc[kb + 1], s_sh[kb + 1]), 0.f);
                    hp[q] = __floats2half2_rn(f.x, f.y);
                }
            }
            *(uint4*)&As2[lr][lk >> 1] = va;
        }
        {
            int gn = n0 + lr;
            uint4 vb = make_uint4(0, 0, 0, 0);
            if (gn < Ncols) vb = *(const uint4*)(Bt + (size_t)gn * KDIM + kk + lk);
            *(uint4*)&Bs2[lr][lk >> 1] = vb;
        }
        __syncthreads();
        uint32_t af[2][4];
        #pragma unroll
        for (int mi = 0; mi < 2; mi++) {
            int rb = mw + mi * 16;
            af[mi][0] = As2[rb + qr][qc];
            af[mi][1] = As2[rb + 8 + qr][qc];
            af[mi][2] = As2[rb + qr][4 + qc];
            af[mi][3] = As2[rb + 8 + qr][4 + qc];
        }
        uint32_t bf[8][2];
        #pragma unroll
        for (int nj = 0; nj < 8; nj++) {
            int nb = nw + nj * 8;
            bf[nj][0] = Bs2[nb + qr][qc];
            bf[nj][1] = Bs2[nb + qr][4 + qc];
        }
        #pragma unroll
        for (int mi = 0; mi < 2; mi++)
            #pragma unroll
            for (int nj = 0; nj < 8; nj++)
                mma_f16(acc[mi][nj], af[mi], bf[nj]);
        __syncthreads();
    }
    // epilogue: store + (optional) fused BN stats
    float st[8][4];
    if (STATS) {
        #pragma unroll
        for (int nj = 0; nj < 8; nj++)
            #pragma unroll
            for (int q = 0; q < 4; q++) st[nj][q] = 0.f;
    }
    #pragma unroll
    for (int mi = 0; mi < 2; mi++) {
        #pragma unroll
        for (int nj = 0; nj < 8; nj++) {
            int colL = nw + nj * 8 + qc * 2;
            int col = n0 + colL;
            int r0 = m0 + mw + mi * 16 + qr;
            int r1 = r0 + 8;
            float v00 = acc[mi][nj][0], v01 = acc[mi][nj][1];
            float v10 = acc[mi][nj][2], v11 = acc[mi][nj][3];
            if (STATS) {
                float b0 = s_b[colL], b1 = s_b[colL + 1];
                v00 += b0; v01 += b1; v10 += b0; v11 += b1;
            }
            if (col < Ncols) {
                if (r0 < M) *(__half2*)(C + (size_t)r0 * Ncols + col) = __floats2half2_rn(v00, v01);
                if (r1 < M) *(__half2*)(C + (size_t)r1 * Ncols + col) = __floats2half2_rn(v10, v11);
            }
            if (STATS) {
                if (r0 >= M) { v00 = 0.f; v01 = 0.f; }
                if (r1 >= M) { v10 = 0.f; v11 = 0.f; }
                st[nj][0] += v00 + v10;
                st[nj][1] += v01 + v11;
                st[nj][2] += v00 * v00 + v10 * v10;
                st[nj][3] += v01 * v01 + v11 * v11;
            }
        }
    }
    if (STATS) {
        #pragma unroll
        for (int nj = 0; nj < 8; nj++) {
            float s0 = st[nj][0], s1 = st[nj][1], q0 = st[nj][2], q1 = st[nj][3];
            #pragma unroll
            for (int o = 4; o < 32; o <<= 1) {
                s0 += __shfl_xor_sync(0xffffffffu, s0, o);
                s1 += __shfl_xor_sync(0xffffffffu, s1, o);
                q0 += __shfl_xor_sync(0xffffffffu, q0, o);
                q1 += __shfl_xor_sync(0xffffffffu, q1, o);
            }
            if (lane < 4) {
                int col = nw + nj * 8 + lane * 2;
                atomicAdd(&g_bnsum[col], s0);
                atomicAdd(&g_bnsum[col + 1], s1);
                atomicAdd(&g_bnsq[col], q0);
                atomicAdd(&g_bnsq[col + 1], q1);
            }
        }
    }
}

// ---------------- BN finalize ----------------
__global__ void k_bnfin(const float* __restrict__ g, const float* __restrict__ be) {
    int t = threadIdx.x;
    if (t < 128) {
        float mean = g_bnsum[t] * (1.f / NV);
        float var = g_bnsq[t] * (1.f / NV) - mean * mean;
        float sc = g[t] * rsqrtf(var + 1e-5f);
        g_bnsc[t] = sc;
        g_bnsh[t] = be[t] - mean * sc;
    }
}

// ---------------- layer-2 epilogue: GAT dots + GCN prescale ----------------
__global__ void k_post2(const float* __restrict__ al, const float* __restrict__ ar) {
    int w = (blockIdx.x * blockDim.x + threadIdx.x) >> 5;
    if (w >= NV) return;
    int lane = threadIdx.x & 31;
    __half* row = g_P2h + (size_t)w * 160;
    float el = 0.f, er = 0.f;
    for (int c = lane; c < 40; c += 32) {
        float f = __half2float(row[120 + c]);
        el = fmaf(f, al[c], el);
        er = fmaf(f, ar[c], er);
    }
    el = warp_sum(el);
    er = warp_sum(er);
    if (lane == 0) { g_el2[w] = el; g_er2[w] = er; }
    float nsv = g_ns[w];
    for (int c = lane; c < 40; c += 32)
        row[80 + c] = __float2half_rn(__half2float(row[80 + c]) * nsv);
}

// ---------------- layer-2 edge aggregation + combine + log_softmax ----------------
__global__ void k_agg2(const float* __restrict__ b21, const float* __restrict__ b22,
                       const float* __restrict__ b23, float* __restrict__ out) {
    int w = (blockIdx.x * blockDim.x + threadIdx.x) >> 5;
    if (w >= NV) return;
    int lane = threadIdx.x & 31;
    int s = g_rowofs[w], e = g_rowofs[w + 1];
    float erv = g_er2[w];
    float mx = -1e30f;
    for (int j = s + lane; j < e; j += 32) mx = fmaxf(mx, g_el2[g_srcs[j]]);
    mx = warp_max(mx);
    float me = lrelu(mx + erv);

    float4 acc = make_float4(0, 0, 0, 0);
    float ss = 0.f;
    bool vec = (lane < 30);
    float gatsel = (lane >= 20 && lane < 30) ? 1.f : 0.f;
    for (int base = s; base < e; base += 32) {
        int j = base + lane;
        int sj = 0;
        float aw = 0.f;
        if (j < e) {
            sj = g_srcs[j];
            aw = __expf(lrelu(g_el2[sj] + erv) - me);
            ss += aw;
        }
        int cnt = min(32, e - base);
        int t = 0;
        for (; t + 4 <= cnt; t += 4) {
            int s0 = __shfl_sync(0xffffffffu, sj, t);
            int s1 = __shfl_sync(0xffffffffu, sj, t + 1);
            int s2 = __shfl_sync(0xffffffffu, sj, t + 2);
            int s3 = __shfl_sync(0xffffffffu, sj, t + 3);
            float A0 = __shfl_sync(0xffffffffu, aw, t);
            float A1 = __shfl_sync(0xffffffffu, aw, t + 1);
            float A2 = __shfl_sync(0xffffffffu, aw, t + 2);
            float A3 = __shfl_sync(0xffffffffu, aw, t + 3);
            if (vec) {
                float m0 = gatsel ? A0 : 1.f;
                float m1 = gatsel ? A1 : 1.f;
                float m2 = gatsel ? A2 : 1.f;
                float m3 = gatsel ? A3 : 1.f;
                uint2 p0 = ((const uint2*)(g_P2h + (size_t)s0 * 160 + 40))[lane];
                uint2 p1 = ((const uint2*)(g_P2h + (size_t)s1 * 160 + 40))[lane];
                uint2 p2 = ((const uint2*)(g_P2h + (size_t)s2 * 160 + 40))[lane];
                uint2 p3 = ((const uint2*)(g_P2h + (size_t)s3 * 160 + 40))[lane];
                float4 u0, u1, u2, u3;
                unpack4h(p0, u0); unpack4h(p1, u1); unpack4h(p2, u2); unpack4h(p3, u3);
                acc.x = fmaf(m0, u0.x, fmaf(m1, u1.x, fmaf(m2, u2.x, fmaf(m3, u3.x, acc.x))));
                acc.y = fmaf(m0, u0.y, fmaf(m1, u1.y, fmaf(m2, u2.y, fmaf(m3, u3.y, acc.y))));
                acc.z = fmaf(m0, u0.z, fmaf(m1, u1.z, fmaf(m2, u2.z, fmaf(m3, u3.z, acc.z))));
                acc.w = fmaf(m0, u0.w, fmaf(m1, u1.w, fmaf(m2, u2.w, fmaf(m3, u3.w, acc.w))));
            }
        }
        for (; t < cnt; t++) {
            int sv = __shfl_sync(0xffffffffu, sj, t);
            float a = __shfl_sync(0xffffffffu, aw, t);
            if (vec) {
                float m = gatsel ? a : 1.f;
                uint2 p = ((const uint2*)(g_P2h + (size_t)sv * 160 + 40))[lane];
                float4 u;
                unpack4h(p, u);
                acc.x = fmaf(m, u.x, acc.x);
                acc.y = fmaf(m, u.y, acc.y);
                acc.z = fmaf(m, u.z, acc.z);
                acc.w = fmaf(m, u.w, acc.w);
            }
        }
    }
    ss = warp_sum(ss);
    float invd = g_invd[w], ndv = g_nd[w];
    float invs = 1.f / fmaxf(ss, 1e-9f);
    int cs = (lane < 10) ? lane : 0;
    float4 sg = shfl4(acc, cs);
    float4 gc = shfl4(acc, cs + 10);
    float4 ga = shfl4(acc, cs + 20);
    float w0 = g_w2[0], w1 = g_w2[1], w2 = g_w2[2];
    float4 val = make_float4(0, 0, 0, 0);
    float lm = -1e30f;
    if (lane < 10) {
        uint2 ps = ((const uint2*)(g_P2h + (size_t)w * 160))[lane];
        float4 self;
        unpack4h(ps, self);
        float4 bs = ((const float4*)b21)[lane];
        float4 bg = ((const float4*)b22)[lane];
        float4 ba = ((const float4*)b23)[lane];
        val.x = w0 * (self.x + sg.x * invd + bs.x) + w1 * (gc.x * ndv + bg.x) + w2 * (ga.x * invs + ba.x);
        val.y = w0 * (self.y + sg.y * invd + bs.y) + w1 * (gc.y * ndv + bg.y) + w2 * (ga.y * invs + ba.y);
        val.z = w0 * (self.z + sg.z * invd + bs.z) + w1 * (gc.z * ndv + bg.z) + w2 * (ga.z * invs + ba.z);
        val.w = w0 * (self.w + sg.w * invd + bs.w) + w1 * (gc.w * ndv + bg.w) + w2 * (ga.w * invs + ba.w);
        lm = fmaxf(fmaxf(val.x, val.y), fmaxf(val.z, val.w));
    }
    #pragma unroll
    for (int o = 8; o; o >>= 1) lm = fmaxf(lm, __shfl_xor_sync(0xffffffffu, lm, o));
    float se = 0.f;
    if (lane < 10)
        se = __expf(val.x - lm) + __expf(val.y - lm) + __expf(val.z - lm) + __expf(val.w - lm);
    #pragma unroll
    for (int o = 8; o; o >>= 1) se += __shfl_xor_sync(0xffffffffu, se, o);
    float lse = lm + logf(se);
    if (lane < 10) {
        float4 r = make_float4(val.x - lse, val.y - lse, val.z - lse, val.w - lse);
        ((float4*)(out + (size_t)w * 40))[lane] = r;
    }
}

// ---------------- launch ----------------
extern "C" void kernel_launch(void* const* d_in, const int* in_sizes, int n_in,
                              void* d_out, int out_size) {
    const float* x    = (const float*)d_in[0];
    const int*   src  = (const int*)d_in[1];
    const int*   dst  = (const int*)d_in[2];
    const float* w11s = (const float*)d_in[3];
    const float* w11n = (const float*)d_in[4];
    const float* b11  = (const float*)d_in[5];
    const float* w12  = (const float*)d_in[6];
    const float* b12  = (const float*)d_in[7];
    const float* w13  = (const float*)d_in[8];
    const float* a13l = (const float*)d_in[9];
    const float* a13r = (const float*)d_in[10];
    const float* b13  = (const float*)d_in[11];
    const float* cw1  = (const float*)d_in[12];
    const float* g    = (const float*)d_in[13];
    const float* be   = (const float*)d_in[14];
    const float* w21s = (const float*)d_in[15];
    const float* w21n = (const float*)d_in[16];
    const float* b21  = (const float*)d_in[17];
    const float* w22  = (const float*)d_in[18];
    const float* b22  = (const float*)d_in[19];
    const float* w23  = (const float*)d_in[20];
    const float* a23l = (const float*)d_in[21];
    const float* a23r = (const float*)d_in[22];
    const float* b23  = (const float*)d_in[23];
    const float* cw2  = (const float*)d_in[24];
    float* out = (float*)d_out;

    __half* dA;  cudaGetSymbolAddress((void**)&dA,  g_A);
    __half* dH;  cudaGetSymbolAddress((void**)&dH,  g_Hh);
    __half* dP2; cudaGetSymbolAddress((void**)&dP2, g_P2h);
    __half* dW1; cudaGetSymbolAddress((void**)&dW1, g_W1h);
    __half* dW2; cudaGetSymbolAddress((void**)&dW2, g_W2h);

    const int TPB = 256;
    int nblkV = (NV + TPB - 1) / TPB;
    int nblkE = (NE + TPB - 1) / TPB;
    int nblkW = (NV + 7) / 8;  // one warp per node

    k_zero<<<nblkV, TPB>>>(cw1, cw2);
    k_deg<<<nblkE, TPB>>>(src, dst);
    k_scan<<<1, 1024>>>();
    k_scatter<<<nblkE, TPB>>>(src, dst);
    k_copyW1<<<(128 * 512) / TPB, TPB>>>(w11s, w11n, w12, w13, b11, b12, b13);
    k_copyW2<<<(160 * 128 + TPB - 1) / TPB, TPB>>>(w21s, w21n, w22, w23);
    k_wvec<<<1, 128>>>(w13, a13l, a13r);

    k_eler1<<<nblkW, TPB>>>(x);
    k_edge1<<<nblkW, TPB>>>();
    gemm_hf<512, false, true><<<dim3((NV + 127) / 128, 1), 256>>>(dA, dW1, dH, NV, 128);

    k_bnfin<<<1, 128>>>(g, be);

    gemm_hf<128, true, false><<<dim3((NV + 127) / 128, 2), 256>>>(dH, dW2, dP2, NV, 160);
    k_post2<<<nblkW, TPB>>>(a23l, a23r);
    k_agg2<<<nblkW, TPB>>>(b21, b22, b23, out);
}